// round 2
// baseline (speedup 1.0000x reference)
#include <cuda_runtime.h>
#include <cstdint>

// Problem constants (fixed shapes from reference setup_inputs)
#define NB 2
#define NS 4
#define NTIME 256
#define NRECV 64
#define NPROB (NB*NS*NRECV)   // 512 independent sinkhorn problems
#define NPTS  256             // points per cloud (= NTIME since SPARSE=1)
#define NSTEPS 24

__device__ __constant__ float kDT     = 0.001f;
__device__ __constant__ float kEPSMIN = 1e-4f;    // BLUR^2
__device__ __constant__ float kRATIO  = 0.25f;    // SCALING^2
#define LOG2E_F 1.4426950408889634f
#define LN2_F   0.6931471805599453f

__device__ float g_div[NPROB];   // per-problem divergence scratch

__device__ __forceinline__ float ex2f(float x){ float y; asm("ex2.approx.ftz.f32 %0, %1;" : "=f"(y) : "f"(x)); return y; }
__device__ __forceinline__ float lg2f(float x){ float y; asm("lg2.approx.ftz.f32 %0, %1;" : "=f"(y) : "f"(x)); return y; }

struct SinkSmem {
    float2 hp[NPTS];   // (col amplitude, precomputed per-col log2-domain term)
    float  xo[NPTS];   // obs amplitudes
    float  xs[NPTS];   // syn amplitudes
    float  F[NPTS], G[NPTS], PX[NPTS], PY[NPTS];
    float  red[32];
};

__device__ __forceinline__ float warpSum(float v){
    #pragma unroll
    for (int o = 16; o; o >>= 1) v += __shfl_xor_sync(0xffffffffu, v, o);
    return v;
}
__device__ __forceinline__ float warpMax(float v){
    #pragma unroll
    for (int o = 16; o; o >>= 1) v = fmaxf(v, __shfl_xor_sync(0xffffffffu, v, o));
    return v;
}
__device__ __forceinline__ float warpMin(float v){
    #pragma unroll
    for (int o = 16; o; o >>= 1) v = fminf(v, __shfl_xor_sync(0xffffffffu, v, o));
    return v;
}

__device__ __forceinline__ float blockSum(float v, float* red){
    v = warpSum(v);
    int w = threadIdx.x >> 5, l = threadIdx.x & 31;
    if (l == 0) red[w] = v;
    __syncthreads();
    if (w == 0) {
        float t = (l < 8) ? red[l] : 0.f;
        t = warpSum(t);
        if (l == 0) red[0] = t;
    }
    __syncthreads();
    v = red[0];
    __syncthreads();
    return v;
}
__device__ __forceinline__ float blockMax(float v, float* red){
    v = warpMax(v);
    int w = threadIdx.x >> 5, l = threadIdx.x & 31;
    if (l == 0) red[w] = v;
    __syncthreads();
    if (w == 0) {
        float t = (l < 8) ? red[l] : -3.4e38f;
        t = warpMax(t);
        if (l == 0) red[0] = t;
    }
    __syncthreads();
    v = red[0];
    __syncthreads();
    return v;
}
__device__ __forceinline__ float blockMin(float v, float* red){
    v = warpMin(v);
    int w = threadIdx.x >> 5, l = threadIdx.x & 31;
    if (l == 0) red[w] = v;
    __syncthreads();
    if (w == 0) {
        float t = (l < 8) ? red[l] : 3.4e38f;
        t = warpMin(t);
        if (l == 0) red[0] = t;
    }
    __syncthreads();
    v = red[0];
    __syncthreads();
    return v;
}

// softmin over 256 columns, log2 domain:
// exponent_full(j) = la2 + pot[j]*ie2 - ie2*(0.5(t_i - t_j)^2 + 0.5(x_i - y_j)^2)
// Factored: per-col term hp[j].y = la2 + pot[j]*ie2 - 0.5*y_j^2*ie2 - c2*j^2
//           per-pair:  + (x_i*ie2)*y_j + (2*c2*i)*j
//           per-row consts (-c2*i^2 - 0.5*x_i^2*ie2) fold back as +0.5*||X_i||^2
// result = -eps*ln2*(m + log2(s)) + 0.5*(t_i^2 + x_i^2)
__device__ __forceinline__ float softmin256(
    const float* __restrict__ pot,   // potentials over columns
    const float* __restrict__ yc,    // column amplitudes
    SinkSmem& sm,
    float xi,                        // this row's amplitude
    float ie2,                       // log2(e)/eps
    float c2,                        // 0.5*DT^2 * ie2
    float eps,
    float la2)                       // -log2(n)
{
    const int tid = threadIdx.x;
    __syncthreads();  // previous users of hp are done
    {
        float yv = yc[tid];
        float jv = (float)tid;
        float t  = la2 + pot[tid]*ie2 - (0.5f*yv*yv)*ie2 - c2*jv*jv;
        sm.hp[tid] = make_float2(yv, t);
    }
    __syncthreads();

    const float xsc = xi * ie2;
    const float u   = 2.0f * c2 * (float)tid;

    // pass 1: max
    float m = -3.4e38f;
    float jf = 0.f;
    #pragma unroll 8
    for (int j = 0; j < NPTS; j++) {
        float2 h = sm.hp[j];
        float a = fmaf(xsc, h.x, h.y);
        a = fmaf(u, jf, a);
        m = fmaxf(m, a);
        jf += 1.f;
    }
    // pass 2: sum of exp2
    float s = 0.f;
    jf = 0.f;
    #pragma unroll 8
    for (int j = 0; j < NPTS; j++) {
        float2 h = sm.hp[j];
        float a = fmaf(xsc, h.x, h.y);
        a = fmaf(u, jf, a);
        s += ex2f(a - m);
        jf += 1.f;
    }

    float ti = (float)tid * kDT;
    return fmaf(-eps * LN2_F, m + lg2f(s), 0.5f * (ti*ti + xi*xi));
}

__global__ void __launch_bounds__(256, 4)
sink_main(const float* __restrict__ syn, const float* __restrict__ obs)
{
    __shared__ SinkSmem sm;
    const int p   = blockIdx.x;         // 0..511
    const int tid = threadIdx.x;        // row index 0..255
    const int bs  = p / NRECV;          // b*NS + s
    const int r   = p - bs * NRECV;

    const size_t base = (size_t)bs * NTIME * NRECV + r;
    const float xobs = obs[base + (size_t)tid * NRECV];
    const float xsyn = syn[base + (size_t)tid * NRECV];
    sm.xo[tid] = xobs;
    sm.xs[tid] = xsyn;
    sm.F[tid] = 0.f; sm.G[tid] = 0.f; sm.PX[tid] = 0.f; sm.PY[tid] = 0.f;
    __syncthreads();

    // trace mask + diameter
    float sabs_o = blockSum(fabsf(xobs), sm.red);
    float sabs_s = blockSum(fabsf(xsyn), sm.red);
    float vmax   = blockMax(fmaxf(xobs, xsyn), sm.red);
    float vmin   = blockMin(fminf(xobs, xsyn), sm.red);
    const bool masked = (sabs_o == 0.f) && (sabs_s == 0.f);

    const float trange   = (float)(NTIME - 1) * kDT;          // t-coordinate range
    const float diameter = fmaxf(trange, vmax - vmin);
    const float eps0     = diameter * diameter;               // P = 2
    const float la2      = -lg2f((float)NPTS);                // log2 of uniform weight

    float fi = 0.f, gi = 0.f, pxi = 0.f, pyi = 0.f;
    float eps_raw = eps0;

    for (int k = 0; k < NSTEPS; k++) {
        const float eps = fmaxf(eps_raw, kEPSMIN);
        eps_raw *= kRATIO;
        const float ie2 = LOG2E_F / eps;
        const float c2  = 0.5f * kDT * kDT * ie2;

        // all four softmins read OLD potentials (scan-step semantics)
        fi  = softmin256(sm.G,  sm.xs, sm, xobs, ie2, c2, eps, la2);
        gi  = softmin256(sm.F,  sm.xo, sm, xsyn, ie2, c2, eps, la2);
        pxi = 0.5f * (pxi + softmin256(sm.PX, sm.xo, sm, xobs, ie2, c2, eps, la2));
        pyi = 0.5f * (pyi + softmin256(sm.PY, sm.xs, sm, xsyn, ie2, c2, eps, la2));

        __syncthreads();   // everyone done reading old potentials
        sm.F[tid] = fi; sm.G[tid] = gi; sm.PX[tid] = pxi; sm.PY[tid] = pyi;
    }
    __syncthreads();

    // S = sum w*(f - px) + sum w*(g - py), w = 1/n
    float contrib = (fi - pxi + gi - pyi) * (1.0f / (float)NPTS);
    float div = blockSum(contrib, sm.red);
    if (tid == 0) g_div[p] = masked ? 0.f : div;
}

// Deterministic final reduction: one block per batch, 256 problems each.
__global__ void __launch_bounds__(256)
sink_finalize(float* __restrict__ out)
{
    __shared__ float red[32];
    const int b = blockIdx.x;
    float v = g_div[b * (NS * NRECV) + threadIdx.x];
    v = blockSum(v, red);
    if (threadIdx.x == 0) out[b] = v;
}

extern "C" void kernel_launch(void* const* d_in, const int* in_sizes, int n_in,
                              void* d_out, int out_size)
{
    const float* syn = (const float*)d_in[0];   // syn_data [B,S,NT,NR]
    const float* obs = (const float*)d_in[1];   // obs_data [B,S,NT,NR]
    float* out = (float*)d_out;                 // [B] float32

    sink_main<<<NPROB, 256>>>(syn, obs);
    sink_finalize<<<NB, 256>>>(out);
}